// round 6
// baseline (speedup 1.0000x reference)
#include <cuda_runtime.h>

// topk_mean (k=2) segment pooling.
// h: [BS, SEQ, EMB] fp32, patch_ids: [BS, SEQ] int32 sorted ascending per batch.
// out: [BS, PNUM, EMB] fp32.
// Semantics (faithful to reference tie-masking loop):
//   max1 = segment max; max2 = max over values strictly != max1 (or -1e9 if none)
//   count==0 -> 0 ; count==1 -> max1 ; count>=2 -> (max1 + max2)/2

#define BS   8
#define SEQ  4096
#define EMB  512
#define PNUM 1024
#define EV4  (EMB / 4)          /* 128 float4 per row */
#define PPC  4                  /* patches per CTA (contiguous) */
#define NEG_INF_V (-1.0e9f)

// starts[b][p] = first token index t with patch_ids[b][t] >= p; starts[b][PNUM]=SEQ.
__device__ int g_starts[BS * (PNUM + 1)];

__global__ void starts_kernel(const int* __restrict__ pid) {
    const int b = blockIdx.y;
    const int t = blockIdx.x * blockDim.x + threadIdx.x;
    if (t >= SEQ) return;
    const int* __restrict__ p = pid + b * SEQ;
    int* __restrict__ st = g_starts + b * (PNUM + 1);

    const int cur  = p[t];
    const int prev = (t == 0) ? -1 : p[t - 1];
    for (int q = prev + 1; q <= cur; ++q) st[q] = t;
    if (t == SEQ - 1) {
        for (int q = cur + 1; q <= PNUM; ++q) st[q] = SEQ;
    }
}

// Branchless running top-2 with tie-skip (v == m1 leaves m2 unchanged).
__device__ __forceinline__ void upd1(float v, float& m1, float& m2) {
    const float nm2 = (v > m1) ? m1 : ((v < m1) ? fmaxf(m2, v) : m2);
    m1 = fmaxf(m1, v);
    m2 = nm2;
}
__device__ __forceinline__ void upd4(const float4 v, float4& m1, float4& m2) {
    upd1(v.x, m1.x, m2.x);
    upd1(v.y, m1.y, m2.y);
    upd1(v.z, m1.z, m2.z);
    upd1(v.w, m1.w, m2.w);
}

__device__ __forceinline__ float4 neg4() {
    return make_float4(-INFINITY, -INFINITY, -INFINITY, -INFINITY);
}

__device__ __forceinline__ float4 patch_result(int cnt, const float4 m1, const float4 m2) {
    if (cnt == 0) return make_float4(0.f, 0.f, 0.f, 0.f);
    if (cnt == 1) return m1;
    float4 r;
    r.x = 0.5f * (m1.x + ((m2.x == -INFINITY) ? NEG_INF_V : m2.x));
    r.y = 0.5f * (m1.y + ((m2.y == -INFINITY) ? NEG_INF_V : m2.y));
    r.z = 0.5f * (m1.z + ((m2.z == -INFINITY) ? NEG_INF_V : m2.z));
    r.w = 0.5f * (m1.w + ((m2.w == -INFINITY) ? NEG_INF_V : m2.w));
    return r;
}

__global__ __launch_bounds__(128)
void pool_kernel(const float4* __restrict__ h4, float4* __restrict__ out4) {
    const int b   = blockIdx.y;
    const int p0  = blockIdx.x * PPC;
    const int tid = threadIdx.x;
    const int* __restrict__ st = g_starts + b * (PNUM + 1);

    int p     = p0;
    int bCur  = st[p0];
    int bNext = st[p0 + 1];
    const int tEnd = st[p0 + PPC];

    // hb/ob pre-offset by this thread's float4 lane
    const float4* __restrict__ hb = h4 + (size_t)b * SEQ * EV4 + tid;
    float4* __restrict__ ob       = out4 + (size_t)b * PNUM * EV4 + tid;

    float4 m1 = neg4();
    float4 m2 = neg4();

    const float4 z4 = make_float4(0.f, 0.f, 0.f, 0.f);
    int t = bCur;

    // Flush patch p (uniform across CTA), advance bounds, reset running top-2.
    // Inside the token loop p never reaches p0+PPC (t < tEnd = st[p0+PPC]
    // keeps the while-condition false once bNext == tEnd), so st[p+1] is safe.
#define FLUSH()                                          \
    do {                                                 \
        ob[(size_t)p * EV4] = patch_result(bNext - bCur, m1, m2); \
        ++p; bCur = bNext; bNext = st[p + 1];            \
        m1 = neg4(); m2 = neg4();                        \
    } while (0)

#define STEP(TT, V)                                      \
    do {                                                 \
        const int tt_ = (TT);                            \
        if (tt_ < tEnd) {                                \
            while (tt_ >= bNext) FLUSH();                \
            upd4((V), m1, m2);                           \
        }                                                \
    } while (0)

    // Prime depth-4 prefetch (rows are contiguous across patch boundaries)
    float4 v0 = (t + 0 < tEnd) ? __ldcs(&hb[(size_t)(t + 0) * EV4]) : z4;
    float4 v1 = (t + 1 < tEnd) ? __ldcs(&hb[(size_t)(t + 1) * EV4]) : z4;
    float4 v2 = (t + 2 < tEnd) ? __ldcs(&hb[(size_t)(t + 2) * EV4]) : z4;
    float4 v3 = (t + 3 < tEnd) ? __ldcs(&hb[(size_t)(t + 3) * EV4]) : z4;

    while (t < tEnd) {
        // issue next 4 loads before consuming current 4 -> sustained MLP ~4-8
        const float4 n0 = (t + 4 < tEnd) ? __ldcs(&hb[(size_t)(t + 4) * EV4]) : z4;
        const float4 n1 = (t + 5 < tEnd) ? __ldcs(&hb[(size_t)(t + 5) * EV4]) : z4;
        const float4 n2 = (t + 6 < tEnd) ? __ldcs(&hb[(size_t)(t + 6) * EV4]) : z4;
        const float4 n3 = (t + 7 < tEnd) ? __ldcs(&hb[(size_t)(t + 7) * EV4]) : z4;

        STEP(t + 0, v0);
        STEP(t + 1, v1);
        STEP(t + 2, v2);
        STEP(t + 3, v3);

        v0 = n0; v1 = n1; v2 = n2; v3 = n3;
        t += 4;
    }

    // Drain: flush remaining patches in [p, p0+PPC) (tail patch with data,
    // plus any trailing empty patches -> zeros).
    while (p < p0 + PPC) {
        ob[(size_t)p * EV4] = patch_result(bNext - bCur, m1, m2);
        ++p; bCur = bNext;
        if (p < p0 + PPC) bNext = st[p + 1];
        m1 = neg4(); m2 = neg4();
    }
#undef STEP
#undef FLUSH
}

extern "C" void kernel_launch(void* const* d_in, const int* in_sizes, int n_in,
                              void* d_out, int out_size) {
    const float* h   = (const float*)d_in[0];
    const int*   pid = (const int*)d_in[1];
    float*       out = (float*)d_out;

    (void)in_sizes; (void)n_in; (void)out_size;

    dim3 g1((SEQ + 255) / 256, BS);
    starts_kernel<<<g1, 256>>>(pid);

    dim3 g2(PNUM / PPC, BS);
    pool_kernel<<<g2, 128>>>((const float4*)h, (float4*)out);
}

// round 7
// speedup vs baseline: 1.1255x; 1.1255x over previous
#include <cuda_runtime.h>

// topk_mean (k=2) segment pooling.
// h: [BS, SEQ, EMB] fp32, patch_ids: [BS, SEQ] int32 sorted ascending per batch.
// out: [BS, PNUM, EMB] fp32.
// Semantics (faithful to reference tie-masking loop):
//   max1 = segment max; max2 = max over values strictly != max1 (or -1e9 if none)
//   count==0 -> 0 ; count==1 -> max1 ; count>=2 -> (max1 + max2)/2

#define BS   8
#define SEQ  4096
#define EMB  512
#define PNUM 1024
#define EV4  (EMB / 4)          /* 128 float4 per row */
#define NEG_INF_V (-1.0e9f)

// starts[b][p] = first token index t with patch_ids[b][t] >= p; starts[b][PNUM]=SEQ.
__device__ int g_starts[BS * (PNUM + 1)];

__global__ void starts_kernel(const int* __restrict__ pid) {
    const int b = blockIdx.y;
    const int t = blockIdx.x * blockDim.x + threadIdx.x;
    if (t >= SEQ) return;
    const int* __restrict__ p = pid + b * SEQ;
    int* __restrict__ st = g_starts + b * (PNUM + 1);

    const int cur  = p[t];
    const int prev = (t == 0) ? -1 : p[t - 1];
    for (int q = prev + 1; q <= cur; ++q) st[q] = t;
    if (t == SEQ - 1) {
        for (int q = cur + 1; q <= PNUM; ++q) st[q] = SEQ;
    }
}

// Branchless running top-2 with tie-skip: v == m1 leaves m2 unchanged.
// Compiles to FSETP + FMNMX + SEL per component — no branches, no divergence.
__device__ __forceinline__ void upd1(float v, float& m1, float& m2) {
    const float nm2 = (v > m1) ? m1 : ((v < m1) ? fmaxf(m2, v) : m2);
    m1 = fmaxf(m1, v);
    m2 = nm2;
}
__device__ __forceinline__ void upd4(const float4 v, float4& m1, float4& m2) {
    upd1(v.x, m1.x, m2.x);
    upd1(v.y, m1.y, m2.y);
    upd1(v.z, m1.z, m2.z);
    upd1(v.w, m1.w, m2.w);
}

__global__ __launch_bounds__(128)
void pool_kernel(const float4* __restrict__ h4, float4* __restrict__ out4) {
    const int p = blockIdx.x;
    const int b = blockIdx.y;
    const int* __restrict__ st = g_starts + b * (PNUM + 1);
    const int start = st[p];
    const int cnt   = st[p + 1] - start;

    float4* __restrict__ o =
        out4 + ((size_t)(b * PNUM + p)) * EV4 + threadIdx.x;

    if (cnt == 0) {
        *o = make_float4(0.f, 0.f, 0.f, 0.f);
        return;
    }

    const float4* __restrict__ hb =
        h4 + ((size_t)b * SEQ + start) * EV4 + threadIdx.x;

    // First row: cnt==1 short-circuits with zero extra work.
    float4 m1 = hb[0];
    if (cnt == 1) {
        *o = m1;
        return;
    }

    float4 m2 = make_float4(-INFINITY, -INFINITY, -INFINITY, -INFINITY);

    // 2-deep rotating prefetch: the load of row t+1 issues before the
    // update consuming row t, keeping 2 LDG.128 in flight per thread.
    float4 v = hb[EV4];                       // row 1
    for (int t = 2; t < cnt; ++t) {
        const float4 vn = hb[(size_t)t * EV4];
        upd4(v, m1, m2);
        v = vn;
    }
    upd4(v, m1, m2);

    float4 r;
    r.x = 0.5f * (m1.x + ((m2.x == -INFINITY) ? NEG_INF_V : m2.x));
    r.y = 0.5f * (m1.y + ((m2.y == -INFINITY) ? NEG_INF_V : m2.y));
    r.z = 0.5f * (m1.z + ((m2.z == -INFINITY) ? NEG_INF_V : m2.z));
    r.w = 0.5f * (m1.w + ((m2.w == -INFINITY) ? NEG_INF_V : m2.w));
    *o = r;
}

extern "C" void kernel_launch(void* const* d_in, const int* in_sizes, int n_in,
                              void* d_out, int out_size) {
    const float* h   = (const float*)d_in[0];
    const int*   pid = (const int*)d_in[1];
    float*       out = (float*)d_out;

    (void)in_sizes; (void)n_in; (void)out_size;

    dim3 g1((SEQ + 255) / 256, BS);
    starts_kernel<<<g1, 256>>>(pid);

    dim3 g2(PNUM, BS);
    pool_kernel<<<g2, 128>>>((const float4*)h, (float4*)out);
}